// round 1
// baseline (speedup 1.0000x reference)
#include <cuda_runtime.h>

#define NLOC 100000
#define NTIME 169
#define NMAX  1000000
#define HMAX  (NLOC*NTIME)           // 16,900,000 possible hashes
#define SCAN_T 256
#define SCAN_I 16
#define SCAN_CHUNK (SCAN_T*SCAN_I)   // 4096
#define SCAN_NB ((HMAX + SCAN_CHUNK - 1)/SCAN_CHUNK)  // 4126

// ---- scratch (device globals: allocation-free under _HX_ENFORCE) ----
__device__ int   g_maxx;
__device__ int   g_nuniq;
__device__ int   d_cntgid[HMAX];     // pass 1: per-hash count; pass 2 (in place): group id
__device__ int   d_hash[NMAX];       // hash per input row
__device__ float d_usum[NMAX*32];    // per-group user-embedding sum
__device__ int   d_ghash[NMAX];      // group -> hash
__device__ int   d_gcnt[NMAX];       // group -> count
__device__ int   d_part[SCAN_NB];    // scan block partials
__device__ float d_locW[NLOC*128];   // loc_emb @ W[:, :64]^T
__device__ float d_timeW[NTIME*128]; // time_emb @ W[:, 64:96]^T

// ---------------- zero scratch ----------------
__global__ void k_zero(int n) {
    const long nc = HMAX/4;                 // int4 words of d_cntgid
    const long total = nc + (long)n*8;      // + float4 words of d_usum
    int4 z = make_int4(0,0,0,0);
    long stride = (long)gridDim.x*blockDim.x;
    for (long i = (long)blockIdx.x*blockDim.x + threadIdx.x; i < total; i += stride) {
        if (i < nc) ((int4*)d_cntgid)[i] = z;
        else        ((int4*)d_usum)[i - nc] = z;
    }
    if (blockIdx.x==0 && threadIdx.x==0) g_maxx = 0;
}

// ---------------- max(x) ----------------
__global__ void k_maxx(const int* __restrict__ x, int n) {
    int m = 0;
    for (int i = blockIdx.x*blockDim.x + threadIdx.x; i < n; i += gridDim.x*blockDim.x)
        m = max(m, x[i]);
    #pragma unroll
    for (int o = 16; o; o >>= 1) m = max(m, __shfl_xor_sync(0xffffffffu, m, o));
    if ((threadIdx.x & 31) == 0) atomicMax(&g_maxx, m);
}

// ---------------- hash + count ----------------
__global__ void k_hash(const int* __restrict__ x, const int* __restrict__ t, int n) {
    int M = g_maxx + 1;
    int i = blockIdx.x*blockDim.x + threadIdx.x;
    if (i < n) {
        int h = t[i]*M + x[i];
        d_hash[i] = h;
        atomicAdd(&d_cntgid[h], 1);
    }
}

// ---------------- scan over occupancy: upsweep ----------------
__global__ void k_upsweep() {
    __shared__ int s[SCAN_T];
    int base = blockIdx.x*SCAN_CHUNK + threadIdx.x*SCAN_I;
    int c = 0;
    #pragma unroll
    for (int j = 0; j < SCAN_I; j++) {
        int idx = base + j;
        if (idx < HMAX) c += (d_cntgid[idx] > 0);
    }
    s[threadIdx.x] = c; __syncthreads();
    for (int off = SCAN_T/2; off; off >>= 1) {
        if (threadIdx.x < off) s[threadIdx.x] += s[threadIdx.x + off];
        __syncthreads();
    }
    if (threadIdx.x == 0) d_part[blockIdx.x] = s[0];
}

// ---------------- scan partials (single block) ----------------
__global__ void k_scanpart() {
    const int P = (SCAN_NB + 1023)/1024;   // 5
    __shared__ int s[1024];
    int t = threadIdx.x;
    int vals[8];
    int v = 0;
    #pragma unroll
    for (int j = 0; j < P; j++) {
        int idx = t*P + j;
        int p = (idx < SCAN_NB) ? d_part[idx] : 0;
        vals[j] = p; v += p;
    }
    s[t] = v; __syncthreads();
    for (int off = 1; off < 1024; off <<= 1) {
        int a = (t >= off) ? s[t - off] : 0;
        __syncthreads();
        s[t] += a;
        __syncthreads();
    }
    int base = s[t] - v;   // exclusive prefix for this thread's chunk
    #pragma unroll
    for (int j = 0; j < P; j++) {
        int idx = t*P + j;
        if (idx < SCAN_NB) { int tmp = vals[j]; d_part[idx] = base; base += tmp; }
    }
    if (t == 1023) g_nuniq = s[1023];
}

// ---------------- downsweep: assign group ids, compact ----------------
__global__ void k_downsweep() {
    __shared__ int s[SCAN_T];
    int tid = threadIdx.x;
    int base = blockIdx.x*SCAN_CHUNK + tid*SCAN_I;
    int cnts[SCAN_I];
    int c = 0;
    #pragma unroll
    for (int j = 0; j < SCAN_I; j++) {
        int idx = base + j;
        cnts[j] = (idx < HMAX) ? d_cntgid[idx] : 0;
        c += (cnts[j] > 0);
    }
    s[tid] = c; __syncthreads();
    for (int off = 1; off < SCAN_T; off <<= 1) {
        int a = (tid >= off) ? s[tid - off] : 0;
        __syncthreads();
        s[tid] += a;
        __syncthreads();
    }
    int g = d_part[blockIdx.x] + (s[tid] - c);
    #pragma unroll
    for (int j = 0; j < SCAN_I; j++) {
        if (cnts[j] > 0) {
            int idx = base + j;
            d_ghash[g] = idx;
            d_gcnt[g]  = cnts[j];
            d_cntgid[idx] = g;     // overwrite count with group id (in place)
            g++;
        }
    }
}

// ---------------- scatter user embeddings (warp per row) ----------------
__global__ void k_scatter(const float* __restrict__ ue, const int* __restrict__ u, int n) {
    int w = (blockIdx.x*blockDim.x + threadIdx.x) >> 5;
    int lane = threadIdx.x & 31;
    if (w >= n) return;
    int g  = d_cntgid[d_hash[w]];
    int ui = u[w];
    atomicAdd(&d_usum[g*32 + lane], ue[ui*32 + lane]);
}

// ---------------- precompute locW = loc_emb @ W[:, :64]^T ----------------
__global__ void k_locW(const float* __restrict__ loc, const float* __restrict__ W) {
    __shared__ float Wl[128*64];
    for (int i = threadIdx.x; i < 128*64; i += blockDim.x) {
        int o = i >> 6, k = i & 63;
        Wl[i] = W[o*128 + k];
    }
    __syncthreads();
    int r = blockIdx.x*blockDim.x + threadIdx.x;
    if (r >= NLOC) return;
    float4 a[16];
    const float4* lr = (const float4*)(loc + (size_t)r*64);
    #pragma unroll
    for (int j = 0; j < 16; j++) a[j] = lr[j];
    const float4* W4 = (const float4*)Wl;
    #pragma unroll 4
    for (int o = 0; o < 128; o++) {
        float acc = 0.f;
        #pragma unroll
        for (int j = 0; j < 16; j++) {
            float4 w = W4[o*16 + j];
            acc += a[j].x*w.x + a[j].y*w.y + a[j].z*w.z + a[j].w*w.w;
        }
        d_locW[(size_t)r*128 + o] = acc;
    }
}

// ---------------- precompute timeW = time_emb @ W[:, 64:96]^T ----------------
__global__ void k_timeW(const float* __restrict__ te, const float* __restrict__ W) {
    __shared__ float Wt[128*32];
    for (int i = threadIdx.x; i < 128*32; i += blockDim.x) {
        int o = i >> 5, k = i & 31;
        Wt[i] = W[o*128 + 64 + k];
    }
    __syncthreads();
    int r = blockIdx.x*blockDim.x + threadIdx.x;
    if (r >= NTIME) return;
    float4 a[8];
    const float4* tr = (const float4*)(te + (size_t)r*32);
    #pragma unroll
    for (int j = 0; j < 8; j++) a[j] = tr[j];
    const float4* W4 = (const float4*)Wt;
    #pragma unroll 4
    for (int o = 0; o < 128; o++) {
        float acc = 0.f;
        #pragma unroll
        for (int j = 0; j < 8; j++) {
            float4 w = W4[o*8 + j];
            acc += a[j].x*w.x + a[j].y*w.y + a[j].z*w.z + a[j].w*w.w;
        }
        d_timeW[r*128 + o] = acc;
    }
}

// ---------------- output: gather + 32-wide dot + tanh ----------------
__global__ __launch_bounds__(128) void k_out(
    const float* __restrict__ W, const float* __restrict__ bias,
    float* __restrict__ out, int n)
{
    int o = threadIdx.x;                   // 128 threads = one output column each
    float wu[32];
    #pragma unroll
    for (int k = 0; k < 32; k++) wu[k] = W[o*128 + 96 + k];
    float bv = bias[o];
    int nu = g_nuniq;
    int M  = g_maxx + 1;
    __shared__ __align__(16) float su[32];
    __shared__ int sh_x, sh_t;
    __shared__ float sh_inv;
    for (int row = blockIdx.x; row < n; row += gridDim.x) {
        if (row < nu) {
            if (o < 32) su[o] = d_usum[row*32 + o];
            if (o == 0) {
                int h = d_ghash[row];
                sh_x = h % M;
                sh_t = h / M;
                sh_inv = 1.0f / (float)d_gcnt[row];
            }
            __syncthreads();
            float acc = d_locW[(size_t)sh_x*128 + o] + d_timeW[sh_t*128 + o] + bv;
            float dot = 0.f;
            const float4* su4 = (const float4*)su;
            #pragma unroll
            for (int j = 0; j < 8; j++) {
                float4 s4 = su4[j];
                dot += s4.x*wu[4*j] + s4.y*wu[4*j+1] + s4.z*wu[4*j+2] + s4.w*wu[4*j+3];
            }
            acc += dot * sh_inv;
            // accurate-enough tanh: (e^{2v}-1)/(e^{2v}+1), clamped
            float v = fminf(fmaxf(acc, -15.f), 15.f);
            float e = __expf(2.f*v);
            out[(size_t)row*128 + o] = (e - 1.f) * __fdividef(1.f, e + 1.f);
            __syncthreads();               // protect smem before next iteration
        } else {
            out[(size_t)row*128 + o] = 0.f;
        }
    }
}

extern "C" void kernel_launch(void* const* d_in, const int* in_sizes, int n_in,
                              void* d_out, int out_size) {
    const float* loc = (const float*)d_in[0];
    const float* te  = (const float*)d_in[1];
    const float* ue  = (const float*)d_in[2];
    const float* W   = (const float*)d_in[3];
    const float* b   = (const float*)d_in[4];
    const int*   x   = (const int*)d_in[5];
    const int*   t   = (const int*)d_in[6];
    const int*   u   = (const int*)d_in[7];
    int n = in_sizes[7];                   // N = 1,000,000
    float* out = (float*)d_out;

    k_zero<<<2048, 256>>>(n);
    k_maxx<<<1024, 256>>>(x, n);
    k_hash<<<(n + 255)/256, 256>>>(x, t, n);
    k_upsweep<<<SCAN_NB, SCAN_T>>>();
    k_scanpart<<<1, 1024>>>();
    k_downsweep<<<SCAN_NB, SCAN_T>>>();
    k_scatter<<<(n*32 + 255)/256, 256>>>(ue, u, n);
    k_locW<<<(NLOC + 255)/256, 256>>>(loc, W);
    k_timeW<<<1, 256>>>(te, W);
    k_out<<<4096, 128>>>(W, b, out, n);
}

// round 2
// speedup vs baseline: 2.0012x; 2.0012x over previous
#include <cuda_runtime.h>

#define NLOC  100000
#define NTIME 169
#define NUSER 50001
#define NMAX  1000000
#define HMAX  (NLOC*NTIME)           // 16,900,000 possible hashes; h = t*NLOC + x
#define SCAN_T 256
#define SCAN_I 16
#define SCAN_CHUNK (SCAN_T*SCAN_I)   // 4096
#define SCAN_NB ((HMAX + SCAN_CHUNK - 1)/SCAN_CHUNK)  // 4126

// ---- scratch (device globals: allocation-free under _HX_ENFORCE) ----
__device__ int   g_nuniq;
__device__ int   d_cntgid[HMAX];     // pass 1: per-hash count; pass 2 (in place): group id
__device__ int   d_hash[NMAX];       // hash per input row
__device__ int   d_ghash[NMAX];      // group -> hash
__device__ int   d_gcnt[NMAX];       // group -> count
__device__ int   d_part[SCAN_NB];    // scan block partials
__device__ float d_locW[NLOC*128];   // loc_emb @ W[:, :64]^T
__device__ float d_timeW[NTIME*128]; // time_emb @ W[:, 64:96]^T + b
__device__ float d_ueW[NUSER*128];   // user_emb @ W[:, 96:128]^T

// ---------------- zero hash-count table ----------------
__global__ void k_zero() {
    const int nc = HMAX/4;           // int4 words (HMAX divisible by 4)
    int4 z = make_int4(0,0,0,0);
    int stride = gridDim.x*blockDim.x;
    for (int i = blockIdx.x*blockDim.x + threadIdx.x; i < nc; i += stride)
        ((int4*)d_cntgid)[i] = z;
}

// ---------------- hash + count ----------------
// NOTE: group ORDER under h = t*M + x is identical for any M > max(x)
// (lexicographic by (t,x)), so M = NLOC is equivalent to the reference's max+1.
__global__ void k_hash(const int* __restrict__ x, const int* __restrict__ t, int n) {
    int i = blockIdx.x*blockDim.x + threadIdx.x;
    if (i < n) {
        int h = t[i]*NLOC + x[i];
        d_hash[i] = h;
        atomicAdd(&d_cntgid[h], 1);
    }
}

// ---------------- scan over occupancy: upsweep (int4 reads) ----------------
__global__ void k_upsweep() {
    __shared__ int s[SCAN_T];
    int base4 = blockIdx.x*(SCAN_CHUNK/4) + threadIdx.x*(SCAN_I/4);
    const int4* c4 = (const int4*)d_cntgid;
    int c = 0;
    #pragma unroll
    for (int j = 0; j < SCAN_I/4; j++) {
        int idx = base4 + j;
        if (idx < HMAX/4) {
            int4 v = c4[idx];
            c += (v.x>0) + (v.y>0) + (v.z>0) + (v.w>0);
        }
    }
    s[threadIdx.x] = c; __syncthreads();
    for (int off = SCAN_T/2; off; off >>= 1) {
        if (threadIdx.x < off) s[threadIdx.x] += s[threadIdx.x + off];
        __syncthreads();
    }
    if (threadIdx.x == 0) d_part[blockIdx.x] = s[0];
}

// ---------------- scan partials (single block) ----------------
__global__ void k_scanpart() {
    const int P = (SCAN_NB + 1023)/1024;   // 5
    __shared__ int s[1024];
    int t = threadIdx.x;
    int vals[8];
    int v = 0;
    #pragma unroll
    for (int j = 0; j < P; j++) {
        int idx = t*P + j;
        int p = (idx < SCAN_NB) ? d_part[idx] : 0;
        vals[j] = p; v += p;
    }
    s[t] = v; __syncthreads();
    for (int off = 1; off < 1024; off <<= 1) {
        int a = (t >= off) ? s[t - off] : 0;
        __syncthreads();
        s[t] += a;
        __syncthreads();
    }
    int base = s[t] - v;   // exclusive prefix for this thread's chunk
    #pragma unroll
    for (int j = 0; j < P; j++) {
        int idx = t*P + j;
        if (idx < SCAN_NB) { int tmp = vals[j]; d_part[idx] = base; base += tmp; }
    }
    if (t == 1023) g_nuniq = s[1023];
}

// ---------------- downsweep: assign group ids, compact (int4 reads) ----------------
__global__ void k_downsweep() {
    __shared__ int s[SCAN_T];
    int tid = threadIdx.x;
    int base = blockIdx.x*SCAN_CHUNK + tid*SCAN_I;
    const int4* c4 = (const int4*)d_cntgid;
    int cnts[SCAN_I];
    int c = 0;
    #pragma unroll
    for (int j = 0; j < SCAN_I/4; j++) {
        int idx4 = base/4 + j;
        int4 v = (idx4 < HMAX/4) ? c4[idx4] : make_int4(0,0,0,0);
        cnts[4*j+0] = v.x; cnts[4*j+1] = v.y; cnts[4*j+2] = v.z; cnts[4*j+3] = v.w;
        c += (v.x>0) + (v.y>0) + (v.z>0) + (v.w>0);
    }
    s[tid] = c; __syncthreads();
    for (int off = 1; off < SCAN_T; off <<= 1) {
        int a = (tid >= off) ? s[tid - off] : 0;
        __syncthreads();
        s[tid] += a;
        __syncthreads();
    }
    int g = d_part[blockIdx.x] + (s[tid] - c);
    #pragma unroll
    for (int j = 0; j < SCAN_I; j++) {
        if (cnts[j] > 0) {
            int idx = base + j;
            d_ghash[g] = idx;
            d_gcnt[g]  = cnts[j];
            d_cntgid[idx] = g;     // overwrite count with group id (in place)
            g++;
        }
    }
}

// ---------------- zero out-rows of multi-count groups (the only rows needing +=) ----
__global__ void k_zeromulti(float* __restrict__ out, int n) {
    int r = blockIdx.x*blockDim.x + threadIdx.x;
    if (r >= n) return;
    if (r < g_nuniq && d_gcnt[r] > 1) {
        float4* o4 = (float4*)(out + (size_t)r*128);
        float4 z = make_float4(0.f,0.f,0.f,0.f);
        #pragma unroll
        for (int j = 0; j < 32; j++) o4[j] = z;
    }
}

// ---------------- precompute ueW = user_emb @ W[:, 96:128]^T ----------------
__global__ void k_ueW(const float* __restrict__ ue, const float* __restrict__ W) {
    __shared__ float Wu[128*32];
    for (int i = threadIdx.x; i < 128*32; i += blockDim.x) {
        int o = i >> 5, k = i & 31;
        Wu[i] = W[o*128 + 96 + k];
    }
    __syncthreads();
    int r = blockIdx.x*blockDim.x + threadIdx.x;
    if (r >= NUSER) return;
    float4 a[8];
    const float4* ur = (const float4*)(ue + (size_t)r*32);
    #pragma unroll
    for (int j = 0; j < 8; j++) a[j] = ur[j];
    const float4* W4 = (const float4*)Wu;
    #pragma unroll 4
    for (int o = 0; o < 128; o++) {
        float acc = 0.f;
        #pragma unroll
        for (int j = 0; j < 8; j++) {
            float4 w = W4[o*8 + j];
            acc += a[j].x*w.x + a[j].y*w.y + a[j].z*w.z + a[j].w*w.w;
        }
        d_ueW[(size_t)r*128 + o] = acc;
    }
}

// ---------------- precompute locW = loc_emb @ W[:, :64]^T ----------------
__global__ void k_locW(const float* __restrict__ loc, const float* __restrict__ W) {
    __shared__ float Wl[128*64];
    for (int i = threadIdx.x; i < 128*64; i += blockDim.x) {
        int o = i >> 6, k = i & 63;
        Wl[i] = W[o*128 + k];
    }
    __syncthreads();
    int r = blockIdx.x*blockDim.x + threadIdx.x;
    if (r >= NLOC) return;
    float4 a[16];
    const float4* lr = (const float4*)(loc + (size_t)r*64);
    #pragma unroll
    for (int j = 0; j < 16; j++) a[j] = lr[j];
    const float4* W4 = (const float4*)Wl;
    #pragma unroll 4
    for (int o = 0; o < 128; o++) {
        float acc = 0.f;
        #pragma unroll
        for (int j = 0; j < 16; j++) {
            float4 w = W4[o*16 + j];
            acc += a[j].x*w.x + a[j].y*w.y + a[j].z*w.z + a[j].w*w.w;
        }
        d_locW[(size_t)r*128 + o] = acc;
    }
}

// ---------------- precompute timeW = time_emb @ W[:, 64:96]^T + b ----------------
__global__ void k_timeW(const float* __restrict__ te, const float* __restrict__ W,
                        const float* __restrict__ b) {
    __shared__ float Wt[128*32];
    for (int i = threadIdx.x; i < 128*32; i += blockDim.x) {
        int o = i >> 5, k = i & 31;
        Wt[i] = W[o*128 + 64 + k];
    }
    __syncthreads();
    int r = blockIdx.x*blockDim.x + threadIdx.x;
    if (r >= NTIME) return;
    float4 a[8];
    const float4* tr = (const float4*)(te + (size_t)r*32);
    #pragma unroll
    for (int j = 0; j < 8; j++) a[j] = tr[j];
    const float4* W4 = (const float4*)Wt;
    #pragma unroll 4
    for (int o = 0; o < 128; o++) {
        float acc = b[o];
        #pragma unroll
        for (int j = 0; j < 8; j++) {
            float4 w = W4[o*8 + j];
            acc += a[j].x*w.x + a[j].y*w.y + a[j].z*w.z + a[j].w*w.w;
        }
        d_timeW[r*128 + o] = acc;
    }
}

// ---------------- scatter pre-projected user rows into out ----------------
// warp per input row; count==1 groups (~97%) use plain coalesced STG.128.
__global__ void k_scatter(const int* __restrict__ u, float* __restrict__ out, int n) {
    int w = (blockIdx.x*blockDim.x + threadIdx.x) >> 5;
    int lane = threadIdx.x & 31;
    if (w >= n) return;
    int g   = d_cntgid[d_hash[w]];
    int cnt = d_gcnt[g];
    float inv = 1.0f / (float)cnt;
    int ui  = u[w];
    float4 v = ((const float4*)d_ueW)[(size_t)ui*32 + lane];
    v.x *= inv; v.y *= inv; v.z *= inv; v.w *= inv;
    float* dst = out + (size_t)g*128 + lane*4;
    if (cnt == 1) {
        *(float4*)dst = v;          // sole member: plain store, no zero needed
    } else {
        atomicAdd(dst + 0, v.x);
        atomicAdd(dst + 1, v.y);
        atomicAdd(dst + 2, v.z);
        atomicAdd(dst + 3, v.w);
    }
}

// ---------------- final: out = tanh(out + locW[x] + timeW[t]) ----------------
__device__ __forceinline__ float tanh_fast(float v) {
    v = fminf(fmaxf(v, -15.f), 15.f);
    float e = __expf(2.f*v);
    return (e - 1.f) * __fdividef(1.f, e + 1.f);
}

__global__ __launch_bounds__(256) void k_out(float* __restrict__ out, int n) {
    int w = (blockIdx.x*blockDim.x + threadIdx.x) >> 5;   // row
    int lane = threadIdx.x & 31;
    if (w >= n) return;
    float4* o4 = (float4*)(out + (size_t)w*128) + lane;
    if (w < g_nuniq) {
        int h  = d_ghash[w];
        int xx = h % NLOC;
        int tt = h / NLOC;
        float4 a  = *o4;
        float4 lw = ((const float4*)d_locW)[(size_t)xx*32 + lane];
        float4 tw = ((const float4*)d_timeW)[tt*32 + lane];
        float4 r;
        r.x = tanh_fast(a.x + lw.x + tw.x);
        r.y = tanh_fast(a.y + lw.y + tw.y);
        r.z = tanh_fast(a.z + lw.z + tw.z);
        r.w = tanh_fast(a.w + lw.w + tw.w);
        *o4 = r;
    } else {
        *o4 = make_float4(0.f,0.f,0.f,0.f);
    }
}

extern "C" void kernel_launch(void* const* d_in, const int* in_sizes, int n_in,
                              void* d_out, int out_size) {
    const float* loc = (const float*)d_in[0];
    const float* te  = (const float*)d_in[1];
    const float* ue  = (const float*)d_in[2];
    const float* W   = (const float*)d_in[3];
    const float* b   = (const float*)d_in[4];
    const int*   x   = (const int*)d_in[5];
    const int*   t   = (const int*)d_in[6];
    const int*   u   = (const int*)d_in[7];
    int n = in_sizes[7];                   // N = 1,000,000
    float* out = (float*)d_out;

    k_zero<<<2048, 256>>>();
    k_hash<<<(n + 255)/256, 256>>>(x, t, n);
    k_upsweep<<<SCAN_NB, SCAN_T>>>();
    k_scanpart<<<1, 1024>>>();
    k_downsweep<<<SCAN_NB, SCAN_T>>>();
    k_zeromulti<<<(n + 255)/256, 256>>>(out, n);
    k_ueW<<<(NUSER + 255)/256, 256>>>(ue, W);
    k_locW<<<(NLOC + 255)/256, 256>>>(loc, W);
    k_timeW<<<1, 256>>>(te, W, b);
    k_scatter<<<(n*32 + 255)/256, 256>>>(u, out, n);
    k_out<<<(n*32 + 255)/256, 256>>>(out, n);
}